// round 11
// baseline (speedup 1.0000x reference)
#include <cuda_runtime.h>
#include <cuda_fp16.h>
#include <cstdint>

// Grouped submanifold sparse conv, N=400000, C_IN=C_OUT=64, GROUPS=4, K=27.
// R11 = R10 (ring + LDS-only fill + smem acc + k-major list + half weights
// + FMA2) with the consume loop made compile-time unrollable:
//  - body list padded to a multiple of 8 with dummy bodies (k=27 -> zeroed
//    weight column, ni = self voxel, j=0: contributes exactly 0)
//  - wave's 8 entries loaded via two LDS.128
//  - #pragma unroll 4 interleaves independent body chains (R10 evidence:
//    duration was bound by the ~120-cyc serial per-body chain, not issue).

#define KOFF 27
#define VPW  16
#define NWARPS 16
#define WAVE 8
#define NSLOT (2 * WAVE)
// half2 weight area, 28 k-slots per group (k=27 is the zero column):
//   wh[g*PGH + k*128 + q*8 + cp], q<8: X=even co, q>=8: Y=odd co
#define KSLOTS 28
#define PGH   (KSLOTS * 128 + 8)        // 3592 words per group
#define W_WORDS (4 * PGH)               // 14368 words (57.5 KB)
#define ACC_F   W_WORDS
#define ACC_PER_WARP (VPW * 32 * 2)     // 1024 floats = 4 KB
#define RING_F  (ACC_F + NWARPS * ACC_PER_WARP)
#define RING_PER_WARP (NSLOT * 64)      // 1024 floats = 4 KB
#define LIST_F  (RING_F + NWARPS * RING_PER_WARP)
#define LIST_CAP 440                    // VPW*27=432 max real + pad, 16B-mult
#define SMEM_WORDS (LIST_F + NWARPS * LIST_CAP)
#define SMEM_BYTES (SMEM_WORDS * 4)     // 216,704 B
#define FULL 0xffffffffu

#define CP_ASYNC16(dst, src) \
    asm volatile("cp.async.cg.shared.global [%0], [%1], 16;" \
                 :: "r"(dst), "l"(src) : "memory")
#define CP_COMMIT() asm volatile("cp.async.commit_group;" ::: "memory")
#define CP_WAIT1()  asm volatile("cp.async.wait_group 1;" ::: "memory")
#define CP_WAIT0()  asm volatile("cp.async.wait_group 0;" ::: "memory")

#define FMA2(d, a, b, c) \
    asm("fma.rn.f32x2 %0, %1, %2, %3;" : "=l"(d) : "l"(a), "l"(b), "l"(c))
#define MUL2(d, a, b) \
    asm("mul.rn.f32x2 %0, %1, %2;" : "=l"(d) : "l"(a), "l"(b))

__device__ __forceinline__ unsigned long long pk2(float a, float b) {
    unsigned long long r;
    asm("mov.b64 %0, {%1, %2};" : "=l"(r) : "f"(a), "f"(b));
    return r;
}
__device__ __forceinline__ void upk2(unsigned long long v, float& a, float& b) {
    asm("mov.b64 {%0, %1}, %2;" : "=f"(a), "=f"(b) : "l"(v));
}

__global__ __launch_bounds__(512, 1)
void subm_conv_r11(const float* __restrict__ feat,
                   const float* __restrict__ weight,
                   const float* __restrict__ bias,
                   const int* __restrict__ nb,
                   float* __restrict__ out,
                   int N, int total_iters, int totwarps)
{
    extern __shared__ float sm[];
    __half2* wh = (__half2*)sm;

    // Stage weights as ci-pair half2: i = ((g*27 + k)*16 + q)*8 + cp
    for (int i = threadIdx.x; i < 4 * KOFF * 128; i += 512) {
        int cp = i & 7;
        int q  = (i >> 3) & 15;
        int gk = i >> 7;                 // g*27 + k
        int g  = gk / KOFF;
        int k  = gk - g * KOFF;
        int ci0 = (q & 7) * 2;
        int co  = 2 * cp + (q >> 3);
        const float* wsrc = weight + ((size_t)gk * 16 + ci0) * 16 + co;
        wh[g * PGH + k * 128 + q * 8 + cp] =
            __floats2half2_rn(wsrc[0], wsrc[16]);
    }
    // Zero column at k=27 (dummy-body target).
    for (int i = threadIdx.x; i < 4 * 128; i += 512) {
        int g = i >> 7;
        wh[g * PGH + 27 * 128 + (i & 127)] = __floats2half2_rn(0.f, 0.f);
    }
    __syncthreads();

    const int lane = threadIdx.x & 31;
    const int wid  = threadIdx.x >> 5;
    const int g    = lane >> 3;          // group
    const int cp   = lane & 7;           // co-pair within group
    const float bx = bias[2 * lane];
    const float by = bias[2 * lane + 1];
    const __half2* whbase = wh + g * PGH + cp;

    float2*   accw  = (float2*)(sm + ACC_F) + wid * (VPW * 32);
    float*    ringw = sm + RING_F + wid * RING_PER_WARP;
    uint32_t* lw    = (uint32_t*)(sm + LIST_F) + wid * LIST_CAP;
    const uint32_t ring_u32 = (uint32_t)__cvta_generic_to_shared(ringw);

    for (int it = blockIdx.x * NWARPS + wid; it < total_iters; it += totwarps) {
        const int vb = it * VPW;
        const int* nbrow = nb + (size_t)vb * KOFF;

        // ---- Phase A: activity mask, prefix scan, emit list (k-major) ----
        unsigned am = 0;
        int idx[VPW];
        #pragma unroll
        for (int j = 0; j < VPW; ++j) {
            int v = vb + j;
            int id = (lane < KOFF && v < N) ? nbrow[j * KOFF + lane] : -1;
            idx[j] = id;
            am |= (id >= 0 ? 1u : 0u) << j;
        }
        int pc = __popc(am);
        int s = pc;
        #pragma unroll
        for (int d = 1; d < 32; d <<= 1) {
            int t = __shfl_up_sync(FULL, s, d);
            if (lane >= d) s += t;
        }
        const int nb_total = __shfl_sync(FULL, s, 31);
        int pos = s - pc;
        unsigned em = am;
        while (em) {
            int j = __ffs(em) - 1; em &= em - 1;
            lw[pos++] = ((uint32_t)idx[j] << 9) | (uint32_t)(j << 5)
                      | (uint32_t)lane;
        }
        // Pad to a multiple of 8 with dummy bodies (k=27, j=0, ni=vb).
        const int padded = (nb_total + 7) & ~7;
        if (lane < padded - nb_total)
            lw[nb_total + lane] = ((uint32_t)vb << 9) | 27u;
        #pragma unroll
        for (int j = 0; j < VPW; ++j)
            accw[j * 32 + lane] = make_float2(bx, by);
        __syncwarp();

        // ---- async fill: wave of 8 bodies, 2 per instruction, LDS-only ----
        auto fill = [&](int wbase, int slotbase) {
            #pragma unroll
            for (int p = 0; p < WAVE; p += 2) {
                int bi = wbase + p + (lane >> 4);
                if (bi < padded) {
                    uint32_t ni = lw[bi] >> 9;
                    uint32_t dst = ring_u32
                                 + (uint32_t)(slotbase + p + (lane >> 4)) * 256u
                                 + (uint32_t)(lane & 15) * 16u;
                    const float* src = feat + (size_t)ni * 64 + (lane & 15) * 4;
                    CP_ASYNC16(dst, src);
                }
            }
            CP_COMMIT();
        };

        fill(0, 0);
        fill(WAVE, WAVE);

        // ---- Phase B: consume, fully padded waves, unrolled bodies ----
        unsigned long long wx[8], wy[8];
        int kcur = -1;
        for (int wbase = 0; wbase < padded; wbase += WAVE) {
            CP_WAIT1();
            __syncwarp();
            const int slotbase = ((wbase >> 3) & 1) * WAVE;
            const uint4 eA = *(const uint4*)(lw + wbase);      // 2 x LDS.128
            const uint4 eB = *(const uint4*)(lw + wbase + 4);
            const uint32_t ee[8] = {eA.x, eA.y, eA.z, eA.w,
                                    eB.x, eB.y, eB.z, eB.w};
            #pragma unroll 4
            for (int p = 0; p < 8; ++p) {
                const uint32_t e = ee[p];               // warp-uniform
                const int k = (int)(e & 31u);
                const int j = (int)((e >> 5) & 15u);
                if (k != kcur) {                        // ~1 per 3.66 bodies
                    kcur = k;
                    const __half2* wp = whbase + k * 128;
                    #pragma unroll
                    for (int q = 0; q < 8; ++q) {
                        float2 fx = __half22float2(wp[q * 8]);
                        wx[q] = pk2(fx.x, fx.y);
                    }
                    #pragma unroll
                    for (int q = 0; q < 8; ++q) {
                        float2 fy = __half22float2(wp[(8 + q) * 8]);
                        wy[q] = pk2(fy.x, fy.y);
                    }
                }
                const ulonglong2* sp = (const ulonglong2*)
                    (ringw + (slotbase + p) * 64 + g * 16);
                ulonglong2 p0 = sp[0], p1 = sp[1], p2 = sp[2], p3 = sp[3];
                unsigned long long ax, ay;
                MUL2(ax, p0.x, wx[0]);        MUL2(ay, p0.x, wy[0]);
                FMA2(ax, p0.y, wx[1], ax);    FMA2(ay, p0.y, wy[1], ay);
                FMA2(ax, p1.x, wx[2], ax);    FMA2(ay, p1.x, wy[2], ay);
                FMA2(ax, p1.y, wx[3], ax);    FMA2(ay, p1.y, wy[3], ay);
                FMA2(ax, p2.x, wx[4], ax);    FMA2(ay, p2.x, wy[4], ay);
                FMA2(ax, p2.y, wx[5], ax);    FMA2(ay, p2.y, wy[5], ay);
                FMA2(ax, p3.x, wx[6], ax);    FMA2(ay, p3.x, wy[6], ay);
                FMA2(ax, p3.y, wx[7], ax);    FMA2(ay, p3.y, wy[7], ay);
                float x0, x1, y0, y1;
                upk2(ax, x0, x1);
                upk2(ay, y0, y1);
                float xs = x0 + x1, ys = y0 + y1;
                float2* ap = accw + j * 32 + lane;      // RMW (issue-ordered)
                float2 a = *ap;
                a.x += xs; a.y += ys;
                *ap = a;
            }
            fill(wbase + 2 * WAVE, slotbase);
        }
        CP_WAIT0();
        __syncwarp();

        // ---- store 16 voxels x 64 channels ----
        #pragma unroll
        for (int j = 0; j < VPW; ++j) {
            int v = vb + j;
            if (v < N)
                ((float2*)(out + (size_t)v * 64))[lane] = accw[j * 32 + lane];
        }
        __syncwarp();
    }
}

extern "C" void kernel_launch(void* const* d_in, const int* in_sizes, int n_in,
                              void* d_out, int out_size)
{
    const float* feat   = (const float*)d_in[0];  // [N, 64]
    const float* weight = (const float*)d_in[1];  // [4, 27, 16, 16]
    const float* bias   = (const float*)d_in[2];  // [64]
    const int*   nb     = (const int*)d_in[3];    // [N, 27]
    float* out = (float*)d_out;

    int N = in_sizes[0] / 64;

    // Idempotent, enqueues no work; safe under graph capture.
    cudaFuncSetAttribute(subm_conv_r11,
                         cudaFuncAttributeMaxDynamicSharedMemorySize, SMEM_BYTES);

    const int blocks = 152;              // 1 CTA/SM (216.7 KB smem)
    const int threads = 512;             // 16 warps
    const int totwarps = blocks * NWARPS;
    int total_iters = (N + VPW - 1) / VPW;

    subm_conv_r11<<<blocks, threads, SMEM_BYTES>>>(feat, weight, bias, nb,
                                                   out, N, total_iters, totwarps);
    (void)n_in; (void)out_size;
}

// round 12
// speedup vs baseline: 1.0362x; 1.0362x over previous
#include <cuda_runtime.h>
#include <cstdint>

// Grouped submanifold sparse conv, N=400000, C_IN=C_OUT=64, GROUPS=4, K=27.
// R12 = R10 pipeline (k-major body list w/ embedded ni, LDS-only cp.async
// fill, smem acc RMW, FMA2 math, VPW=16) with the weight reload de-fattened:
// weights staged in smem as packed fp32 ci-pairs (the exact 64-bit FMA2
// operand), so a k-run reload is 16 bare LDS.64 — no half2 cvt, no pack
// (R9-R11 paid ~70 slots/reload on the serial path; now ~36).
// Full fp32 precision restored. Budget: 110.8K wt + 60K acc + 30K ring +
// 25.3K list = 223.6KB -> 15 warps (480 thr), 1 CTA/SM.

#define KOFF 27
#define VPW  16
#define NWARPS 15
#define THREADS (NWARPS * 32)
#define WAVE 4
#define NSLOT (2 * WAVE)                // 8 slots x 256 B per warp
// fp32-pair weight area: ws2[g*PGF2 + k*128 + q*8 + cp] (float2)
//   q in 0..15: q<8 -> X block (even co), q>=8 -> Y block (odd co)
//   pair = (w[g][k][2q'][co], w[g][k][2q'+1][co]), q'=q&7, co=2cp+(q>>3)
#define PGF2  (KOFF * 128 + 8)          // 3464 float2 per group (64B pad)
#define W_FLOATS (4 * PGF2 * 2)         // 27712 floats = 110,848 B
#define ACC_F   W_FLOATS
#define ACC_PER_WARP (VPW * 32 * 2)     // 1024 floats = 4 KB
#define RING_F  (ACC_F + NWARPS * ACC_PER_WARP)
#define RING_PER_WARP (NSLOT * 64)      // 512 floats = 2 KB
#define LIST_F  (RING_F + NWARPS * RING_PER_WARP)
#define LIST_CAP 432                    // = VPW * 27
#define SMEM_WORDS (LIST_F + NWARPS * LIST_CAP)
#define SMEM_BYTES (SMEM_WORDS * 4)     // 228,928 B
#define FULL 0xffffffffu

#define CP_ASYNC16(dst, src) \
    asm volatile("cp.async.cg.shared.global [%0], [%1], 16;" \
                 :: "r"(dst), "l"(src) : "memory")
#define CP_COMMIT() asm volatile("cp.async.commit_group;" ::: "memory")
#define CP_WAIT1()  asm volatile("cp.async.wait_group 1;" ::: "memory")
#define CP_WAIT0()  asm volatile("cp.async.wait_group 0;" ::: "memory")

#define FMA2(d, a, b, c) \
    asm("fma.rn.f32x2 %0, %1, %2, %3;" : "=l"(d) : "l"(a), "l"(b), "l"(c))
#define MUL2(d, a, b) \
    asm("mul.rn.f32x2 %0, %1, %2;" : "=l"(d) : "l"(a), "l"(b))

__device__ __forceinline__ void upk2(unsigned long long v, float& a, float& b) {
    asm("mov.b64 {%0, %1}, %2;" : "=f"(a), "=f"(b) : "l"(v));
}

__global__ __launch_bounds__(THREADS, 1)
void subm_conv_r12(const float* __restrict__ feat,
                   const float* __restrict__ weight,
                   const float* __restrict__ bias,
                   const int* __restrict__ nb,
                   float* __restrict__ out,
                   int N, int total_iters, int totwarps)
{
    extern __shared__ float sm[];
    float2* ws2 = (float2*)sm;

    // Stage weights as fp32 ci-pairs: i = ((g*27 + k)*16 + q)*8 + cp
    for (int i = threadIdx.x; i < 4 * KOFF * 128; i += THREADS) {
        int cp = i & 7;
        int q  = (i >> 3) & 15;
        int gk = i >> 7;                 // g*27 + k
        int g  = gk / KOFF;
        int k  = gk - g * KOFF;
        int ci0 = (q & 7) * 2;
        int co  = 2 * cp + (q >> 3);
        const float* wsrc = weight + ((size_t)gk * 16 + ci0) * 16 + co;
        ws2[g * PGF2 + k * 128 + q * 8 + cp] = make_float2(wsrc[0], wsrc[16]);
    }
    __syncthreads();

    const int lane = threadIdx.x & 31;
    const int wid  = threadIdx.x >> 5;
    const int g    = lane >> 3;          // group
    const int cp   = lane & 7;           // co-pair within group
    const float bx = bias[2 * lane];
    const float by = bias[2 * lane + 1];
    const unsigned long long* wsbase =
        (const unsigned long long*)(ws2 + g * PGF2 + cp);

    float2*   accw  = (float2*)(sm + ACC_F) + wid * (VPW * 32);
    float*    ringw = sm + RING_F + wid * RING_PER_WARP;
    uint32_t* lw    = (uint32_t*)(sm + LIST_F) + wid * LIST_CAP;
    const uint32_t ring_u32 = (uint32_t)__cvta_generic_to_shared(ringw);

    for (int it = blockIdx.x * NWARPS + wid; it < total_iters; it += totwarps) {
        const int vb = it * VPW;
        const int* nbrow = nb + (size_t)vb * KOFF;

        // ---- Phase A: activity mask, prefix scan, emit list (k-major) ----
        unsigned am = 0;
        int idx[VPW];
        #pragma unroll
        for (int j = 0; j < VPW; ++j) {
            int v = vb + j;
            int id = (lane < KOFF && v < N) ? nbrow[j * KOFF + lane] : -1;
            idx[j] = id;
            am |= (id >= 0 ? 1u : 0u) << j;
        }
        int pc = __popc(am);
        int s = pc;
        #pragma unroll
        for (int d = 1; d < 32; d <<= 1) {
            int t = __shfl_up_sync(FULL, s, d);
            if (lane >= d) s += t;
        }
        const int nb_total = __shfl_sync(FULL, s, 31);
        int pos = s - pc;
        unsigned em = am;
        while (em) {
            int j = __ffs(em) - 1; em &= em - 1;
            lw[pos++] = ((uint32_t)idx[j] << 9) | (uint32_t)(j << 5)
                      | (uint32_t)lane;
        }
        #pragma unroll
        for (int j = 0; j < VPW; ++j)
            accw[j * 32 + lane] = make_float2(bx, by);
        __syncwarp();

        // ---- async fill: wave of 4 bodies, 2 per instruction, LDS-only ----
        auto fill = [&](int wbase, int slotbase) {
            #pragma unroll
            for (int p = 0; p < WAVE; p += 2) {
                int bi = wbase + p + (lane >> 4);
                if (bi < nb_total) {
                    uint32_t ni = lw[bi] >> 9;
                    uint32_t dst = ring_u32
                                 + (uint32_t)(slotbase + p + (lane >> 4)) * 256u
                                 + (uint32_t)(lane & 15) * 16u;
                    const float* src = feat + (size_t)ni * 64 + (lane & 15) * 4;
                    CP_ASYNC16(dst, src);
                }
            }
            CP_COMMIT();
        };

        fill(0, 0);
        fill(WAVE, WAVE);

        // ---- Phase B: dense consume ----
        unsigned long long wx[8], wy[8];
        int kcur = -1;
        for (int wbase = 0; wbase < nb_total; wbase += WAVE) {
            CP_WAIT1();
            __syncwarp();
            const int slotbase = ((wbase >> 2) & 1) * WAVE;
            const int cend = (wbase + WAVE < nb_total) ? wbase + WAVE : nb_total;
            for (int i = wbase; i < cend; ++i) {
                const uint32_t e = lw[i];               // warp-uniform
                const int k = (int)(e & 31u);
                const int j = (int)((e >> 5) & 15u);
                if (k != kcur) {                        // ~1 per 3.66 bodies
                    kcur = k;
                    const unsigned long long* wp = wsbase + k * 128;
                    #pragma unroll
                    for (int q = 0; q < 8; ++q) wx[q] = wp[q * 8];       // LDS.64
                    #pragma unroll
                    for (int q = 0; q < 8; ++q) wy[q] = wp[64 + q * 8];  // LDS.64
                }
                const ulonglong2* sp = (const ulonglong2*)
                    (ringw + (slotbase + (i - wbase)) * 64 + g * 16);
                ulonglong2 p0 = sp[0], p1 = sp[1], p2 = sp[2], p3 = sp[3];
                unsigned long long ax, ay;
                MUL2(ax, p0.x, wx[0]);        MUL2(ay, p0.x, wy[0]);
                FMA2(ax, p0.y, wx[1], ax);    FMA2(ay, p0.y, wy[1], ay);
                FMA2(ax, p1.x, wx[2], ax);    FMA2(ay, p1.x, wy[2], ay);
                FMA2(ax, p1.y, wx[3], ax);    FMA2(ay, p1.y, wy[3], ay);
                FMA2(ax, p2.x, wx[4], ax);    FMA2(ay, p2.x, wy[4], ay);
                FMA2(ax, p2.y, wx[5], ax);    FMA2(ay, p2.y, wy[5], ay);
                FMA2(ax, p3.x, wx[6], ax);    FMA2(ay, p3.x, wy[6], ay);
                FMA2(ax, p3.y, wx[7], ax);    FMA2(ay, p3.y, wy[7], ay);
                float x0, x1, y0, y1;
                upk2(ax, x0, x1);
                upk2(ay, y0, y1);
                float xs = x0 + x1, ys = y0 + y1;
                float2* ap = accw + j * 32 + lane;      // same-lane RMW
                float2 a = *ap;
                a.x += xs; a.y += ys;
                *ap = a;
            }
            fill(wbase + 2 * WAVE, slotbase);
        }
        CP_WAIT0();
        __syncwarp();

        // ---- store 16 voxels x 64 channels ----
        #pragma unroll
        for (int j = 0; j < VPW; ++j) {
            int v = vb + j;
            if (v < N)
                ((float2*)(out + (size_t)v * 64))[lane] = accw[j * 32 + lane];
        }
        __syncwarp();
    }
}

extern "C" void kernel_launch(void* const* d_in, const int* in_sizes, int n_in,
                              void* d_out, int out_size)
{
    const float* feat   = (const float*)d_in[0];  // [N, 64]
    const float* weight = (const float*)d_in[1];  // [4, 27, 16, 16]
    const float* bias   = (const float*)d_in[2];  // [64]
    const int*   nb     = (const int*)d_in[3];    // [N, 27]
    float* out = (float*)d_out;

    int N = in_sizes[0] / 64;

    // Idempotent, enqueues no work; safe under graph capture.
    cudaFuncSetAttribute(subm_conv_r12,
                         cudaFuncAttributeMaxDynamicSharedMemorySize, SMEM_BYTES);

    const int blocks = 152;              // 1 CTA/SM (223.6 KB smem)
    const int totwarps = blocks * NWARPS;
    int total_iters = (N + VPW - 1) / VPW;

    subm_conv_r12<<<blocks, THREADS, SMEM_BYTES>>>(feat, weight, bias, nb,
                                                   out, N, total_iters, totwarps);
    (void)n_in; (void)out_size;
}